// round 4
// baseline (speedup 1.0000x reference)
#include <cuda_runtime.h>
#include <math.h>

#define T 4096
#define BS 128
#define CAPC 1024           // per-list shared coef cache (float2)

typedef unsigned long long ull;

// ---------------- device scratch ----------------
__device__ float2 g_S2[(size_t)BS * 5 * T];   // cumsum of X, planes (b, plane, t), transpose-closed pairing
__device__ float2 g_coefF[T + 8];             // dense tap coefs (df, dfp), run-ordered
__device__ float2 g_coefG[T + 8];
__device__ int4   g_runF[2052];               // (m0, len, coefBase, 0)
__device__ int4   g_runG[2052];
__device__ int    g_nF, g_nG, g_nrunF, g_nrunG;

struct FParams {
    const float* W1[4];
    const float* b1[4];
    const float* W2[4];
    const float* b2[4];
};

// ---------------- math helpers ----------------
__device__ __forceinline__ void make_E(float z0, float z1,
                                       float a1x, float a1y, float a1z,
                                       float a2x, float a2y, float a2z,
                                       float e[9]) {
    float wx = a1x * z0 + a2x * z1;
    float wy = a1y * z0 + a2y * z1;
    float wz = a1z * z0 + a2z * z1;
    float th2 = wx * wx + wy * wy + wz * wz;
    float s, c, c2;
    if (th2 > 1e-6f) {
        float th = sqrtf(th2);
        float sn, cn;
        sincosf(th, &sn, &cn);
        s = sn / th;
        c = cn;
        c2 = (1.f - cn) / th2;
    } else {
        s = 1.f - th2 * (1.f / 6.f);
        c = 1.f - th2 * 0.5f;
        c2 = 0.5f - th2 * (1.f / 24.f);
    }
    e[0] = c + c2 * wx * wx;      e[1] = c2 * wx * wy - s * wz; e[2] = c2 * wx * wz + s * wy;
    e[3] = c2 * wy * wx + s * wz; e[4] = c + c2 * wy * wy;      e[5] = c2 * wy * wz - s * wx;
    e[6] = c2 * wz * wx - s * wy; e[7] = c2 * wz * wy + s * wx; e[8] = c + c2 * wz * wz;
}

__device__ __forceinline__ void mul_right(float X[9], const float e[9]) {
    #pragma unroll
    for (int r = 0; r < 3; r++) {
        float x0 = X[r * 3], x1 = X[r * 3 + 1], x2 = X[r * 3 + 2];
        X[r * 3 + 0] = x0 * e[0] + x1 * e[3] + x2 * e[6];
        X[r * 3 + 1] = x0 * e[1] + x1 * e[4] + x2 * e[7];
        X[r * 3 + 2] = x0 * e[2] + x1 * e[5] + x2 * e[8];
    }
}

__device__ __forceinline__ void mul_left(float X[9], const float L[9]) {
    #pragma unroll
    for (int cc = 0; cc < 3; cc++) {
        float x0 = X[cc], x1 = X[3 + cc], x2 = X[6 + cc];
        X[cc]     = L[0] * x0 + L[1] * x1 + L[2] * x2;
        X[3 + cc] = L[3] * x0 + L[4] * x1 + L[5] * x2;
        X[6 + cc] = L[6] * x0 + L[7] * x1 + L[8] * x2;
    }
}

// ---------------- K_main: filters/runs block (bid==BS) + pathdev blocks ----------------
__device__ void build_runs(const int* tapm, int cnt, int4* runs, int* nrun_out) {
    int nr = 0, i = 0;
    while (i < cnt) {
        int m0 = tapm[i];
        int j = i + 1;
        while (j < cnt && tapm[j] == tapm[j - 1] + 1) j++;
        runs[nr] = make_int4(m0, j - i, i, 0);
        nr++;
        i = j;
    }
    runs[nr] = make_int4(0x7fffffff, 0, 0, 0);  // sentinel
    *nrun_out = nr;
}

__global__ void __launch_bounds__(256) k_main(const float* __restrict__ x_data,
                                              const float* __restrict__ A1,
                                              const float* __restrict__ A2,
                                              FParams p) {
    extern __shared__ float smem[];
    int tid = threadIdx.x;

    if (blockIdx.x == BS) {
        float* sh = smem;                         // [4][T]
        int* tapmF = (int*)(smem + 4 * T);        // [T]
        int* tapmG = tapmF + T;                   // [T]
        for (int idx = tid; idx < 4 * T; idx += 256) {
            int f = idx >> 12;
            int i = idx & (T - 1);
            float tt = (f < 2) ? (float)(T - 1 - i) : (float)i;  // f, fp reversed
            const float* W1 = p.W1[f];
            const float* b1 = p.b1[f];
            const float* W2 = p.W2[f];
            float acc = p.b2[f][0];
            #pragma unroll
            for (int u = 0; u < 5; u++)
                acc += W2[u] * tanhf(W1[u] * tt + b1[u]);
            sh[f * T + i] = acc;
        }
        __syncthreads();
        int wid = tid >> 5, lane = tid & 31;
        if (wid < 2) {
            int fa = wid * 2, fb = fa + 1;
            float2* cdst = wid ? g_coefG : g_coefF;
            int* mdst = wid ? tapmG : tapmF;
            int cnt = 0;
            for (int base = 0; base < T; base += 32) {
                int m = base + lane;
                float da = (m == 0) ? sh[fa * T] : sh[fa * T + m] - sh[fa * T + m - 1];
                float db = (m == 0) ? sh[fb * T] : sh[fb * T + m] - sh[fb * T + m - 1];
                int act = (da != 0.f) || (db != 0.f);
                unsigned mask = __ballot_sync(0xffffffffu, act);
                if (act) {
                    int pos = cnt + __popc(mask & ((1u << lane) - 1u));
                    cdst[pos] = make_float2(da, db);
                    mdst[pos] = m;
                }
                cnt += __popc(mask);
            }
            if (lane == 0) {
                if (wid == 0) g_nF = cnt; else g_nG = cnt;
            }
        }
        __syncthreads();
        if (tid == 0)  build_runs(tapmF, g_nF, g_runF, &g_nrunF);
        if (tid == 32) build_runs(tapmG, g_nG, g_runG, &g_nrunG);
        return;
    }

    // ---- pathdev block ----
    float* sx  = smem;          // 8192 floats
    float* smf = smem + 8192;   // 256*9 floats
    int b = blockIdx.x;

    {
        const float4* src = (const float4*)(x_data + (size_t)b * T * 2);
        float4* dst = (float4*)sx;
        #pragma unroll
        for (int i = tid; i < T * 2 / 4; i += 256) dst[i] = src[i];
    }

    float a1x = A1[7] - A1[5], a1y = A1[2] - A1[6], a1z = A1[3] - A1[1];
    float a2x = A2[7] - A2[5], a2y = A2[2] - A2[6], a2z = A2[3] - A2[1];
    __syncthreads();

    const int C = T / 256;  // 16
    int t0 = tid * C;

    float P[9] = {1, 0, 0, 0, 1, 0, 0, 0, 1};
    float CS[9] = {0, 0, 0, 0, 0, 0, 0, 0, 0};
    for (int i = 0; i < C; i++) {
        int t = t0 + i;
        if (t > 0) {
            float e[9];
            make_E(sx[2 * t], sx[2 * t + 1], a1x, a1y, a1z, a2x, a2y, a2z, e);
            mul_right(P, e);
        }
        #pragma unroll
        for (int d = 0; d < 9; d++) CS[d] += P[d];
    }

    float Pw[9];
    #pragma unroll
    for (int d = 0; d < 9; d++) { Pw[d] = P[d]; smf[tid * 9 + d] = P[d]; }
    for (int off = 1; off < 256; off <<= 1) {
        __syncthreads();
        float L[9];
        int has = tid >= off;
        if (has) {
            #pragma unroll
            for (int d = 0; d < 9; d++) L[d] = smf[(tid - off) * 9 + d];
        }
        __syncthreads();
        if (has) {
            mul_left(Pw, L);
            #pragma unroll
            for (int d = 0; d < 9; d++) smf[tid * 9 + d] = Pw[d];
        }
    }
    __syncthreads();
    float PM[9];
    if (tid > 0) {
        #pragma unroll
        for (int d = 0; d < 9; d++) PM[d] = smf[(tid - 1) * 9 + d];
    } else {
        #pragma unroll
        for (int d = 0; d < 9; d++) PM[d] = (d == 0 || d == 4 || d == 8) ? 1.f : 0.f;
    }
    __syncthreads();

    float CSg[9];
    #pragma unroll
    for (int i = 0; i < 3; i++)
        #pragma unroll
        for (int j = 0; j < 3; j++)
            CSg[3 * i + j] = PM[3 * i + 0] * CS[0 + j] + PM[3 * i + 1] * CS[3 + j] + PM[3 * i + 2] * CS[6 + j];

    float Aw[9];
    #pragma unroll
    for (int d = 0; d < 9; d++) { Aw[d] = CSg[d]; smf[tid * 9 + d] = CSg[d]; }
    for (int off = 1; off < 256; off <<= 1) {
        __syncthreads();
        float L[9];
        int has = tid >= off;
        if (has) {
            #pragma unroll
            for (int d = 0; d < 9; d++) L[d] = smf[(tid - off) * 9 + d];
        }
        __syncthreads();
        if (has) {
            #pragma unroll
            for (int d = 0; d < 9; d++) { Aw[d] += L[d]; smf[tid * 9 + d] = Aw[d]; }
        }
    }
    __syncthreads();
    float PS[9];
    if (tid > 0) {
        #pragma unroll
        for (int d = 0; d < 9; d++) PS[d] = smf[(tid - 1) * 9 + d];
    } else {
        #pragma unroll
        for (int d = 0; d < 9; d++) PS[d] = 0.f;
    }

    float X[9];
    #pragma unroll
    for (int d = 0; d < 9; d++) X[d] = PM[d];
    float2* Sb = g_S2 + (size_t)b * 5 * T;
    for (int i = 0; i < C; i++) {
        int t = t0 + i;
        if (t > 0) {
            float e[9];
            make_E(sx[2 * t], sx[2 * t + 1], a1x, a1y, a1z, a2x, a2y, a2z, e);
            mul_right(X, e);
        }
        #pragma unroll
        for (int d = 0; d < 9; d++) PS[d] += X[d];
        // transpose-closed pairing: (0,4) (1,3) (8,-) (2,6) (5,7)
        Sb[0 * T + t] = make_float2(PS[0], PS[4]);
        Sb[1 * T + t] = make_float2(PS[1], PS[3]);
        Sb[2 * T + t] = make_float2(PS[8], 0.f);
        Sb[3 * T + t] = make_float2(PS[2], PS[6]);
        Sb[4 * T + t] = make_float2(PS[5], PS[7]);
    }
}

// ---------------- K_final: sliding-window register FIR ----------------
__device__ __forceinline__ ull packf(float a) {
    ull r;
    asm("mov.b64 %0, {%1, %1};" : "=l"(r) : "f"(a));
    return r;
}
__device__ __forceinline__ ull f2bits(float2 v) {
    ull r;
    asm("mov.b64 %0, {%1, %2};" : "=l"(r) : "f"(v.x), "f"(v.y));
    return r;
}
__device__ __forceinline__ void fma2(ull& acc, ull a, ull b) {
    asm("fma.rn.f32x2 %0, %1, %2, %0;" : "+l"(acc) : "l"(a), "l"(b));
}
__device__ __forceinline__ void unpck(ull v, float& lo, float& hi) {
    asm("mov.b64 {%0, %1}, %2;" : "=f"(lo), "=f"(hi) : "l"(v));
}

template <int NP>
__device__ __forceinline__ void ld_guard(const float2* __restrict__ sS, int pb,
                                         int r, ull W[NP][4], int slot) {
    bool v = r >= 0;
    int rr = v ? r : 0;
    #pragma unroll
    for (int p = 0; p < NP; p++) {
        float2 d = sS[(pb + p) * T + rr];
        W[p][slot] = v ? f2bits(d) : 0ULL;
    }
}

template <int NP, bool SH>
__device__ void walk(const float2* __restrict__ sS, int pb,
                     const float2* __restrict__ coefs,
                     const int4* __restrict__ runs, int nrun,
                     int k0, int warpKmax,
                     ull accA[NP][4], ull accB[NP][4]) {
    for (int ri = 0; ri < nrun; ri++) {
        int4 rn = __ldg(&runs[ri]);
        int m0 = rn.x;
        if (m0 > warpKmax) break;
        int L = min(rn.y, warpKmax - m0 + 1);
        const float2* cc = coefs + rn.z;

        ull W[NP][4];
        #pragma unroll
        for (int j = 0; j < 4; j++)
            ld_guard<NP>(sS, pb, k0 + j - m0, W, j);

        int i = 0;
        for (; i + 4 <= L; i += 4) {
            #pragma unroll
            for (int u = 0; u < 4; u++) {
                float2 cf = SH ? cc[i + u] : __ldg(&cc[i + u]);
                ull cy = packf(cf.x), cz = packf(cf.y);
                #pragma unroll
                for (int p = 0; p < NP; p++)
                    #pragma unroll
                    for (int j = 0; j < 4; j++) {
                        ull w = W[p][(j - u) & 3];
                        fma2(accA[p][j], w, cy);
                        fma2(accB[p][j], w, cz);
                    }
                ld_guard<NP>(sS, pb, k0 - m0 - (i + u) - 1, W, (3 - u) & 3);
            }
        }
        #pragma unroll
        for (int u = 0; u < 3; u++) {
            if (i + u < L) {
                float2 cf = SH ? cc[i + u] : __ldg(&cc[i + u]);
                ull cy = packf(cf.x), cz = packf(cf.y);
                #pragma unroll
                for (int p = 0; p < NP; p++)
                    #pragma unroll
                    for (int j = 0; j < 4; j++) {
                        ull w = W[p][(j - u) & 3];
                        fma2(accA[p][j], w, cy);
                        fma2(accB[p][j], w, cz);
                    }
                ld_guard<NP>(sS, pb, k0 - m0 - (i + u) - 1, W, (3 - u) & 3);
            }
        }
    }
}

template <int NP>
__device__ __forceinline__ void combine_write(float* __restrict__ sOut, int lt0, int pb,
                                              ull aF[NP][4], ull aFp[NP][4],
                                              ull aG[NP][4], ull aGp[NP][4]) {
    // plane P: (chx, chy), swap flag for F terms
    const int  chx[5] = {0, 1, 8, 2, 5};
    const int  chy[5] = {4, 3, -1, 6, 7};
    const bool SW[5]  = {false, true, false, true, true};
    #pragma unroll
    for (int p = 0; p < NP; p++) {
        int P = pb + p;
        #pragma unroll
        for (int j = 0; j < 4; j++) {
            float fLo, fHi, pLo, pHi, gLo, gHi, qLo, qHi;
            unpck(aF[p][j],  fLo, fHi);
            unpck(aFp[p][j], pLo, pHi);
            unpck(aG[p][j],  gLo, gHi);
            unpck(aGp[p][j], qLo, qHi);
            float FL = SW[P] ? fHi : fLo, FH = SW[P] ? fLo : fHi;
            float PL = SW[P] ? pHi : pLo, PH = SW[P] ? pLo : pHi;
            int lt = lt0 + j;
            sOut[lt * 9 + chx[P]] = FL * gLo + PL * qLo;
            if (chy[P] >= 0)
                sOut[lt * 9 + chy[P]] = FH * gHi + PH * qHi;
        }
    }
}

__global__ void __launch_bounds__(256, 1) k_final(float* __restrict__ out) {
    extern __shared__ __align__(16) char smem_raw[];
    float2* sS   = (float2*)smem_raw;                 // 5*T float2 = 163840 B
    float2* sCF  = sS + 5 * T;                        // CAPC = 8192 B
    float2* sCG  = sCF + CAPC;                        // 8192 B
    float*  sOut = (float*)(sCG + CAPC);              // 1024*9 floats = 36864 B

    int q = blockIdx.x, b = blockIdx.y, tid = threadIdx.x;
    int kb = q * 1024;
    int k0 = kb + tid * 4;
    int warpKmax = kb + ((tid >> 5) + 1) * 128 - 1;
    int nrows = kb + 1024;

    // stage S planes [0, nrows)
    {
        const float2* src = g_S2 + (size_t)b * 5 * T;
        #pragma unroll
        for (int pp = 0; pp < 5; pp++) {
            float4* d4 = (float4*)(sS + pp * T);
            const float4* s4 = (const float4*)(src + pp * T);
            for (int i = tid; i < nrows / 2; i += 256) d4[i] = s4[i];
        }
    }
    int nF = g_nF, nG = g_nG, nrF = g_nrunF, nrG = g_nrunG;
    bool fitF = nF <= CAPC, fitG = nG <= CAPC;
    if (fitF) for (int i = tid; i < nF; i += 256) sCF[i] = g_coefF[i];
    if (fitG) for (int i = tid; i < nG; i += 256) sCG[i] = g_coefG[i];
    __syncthreads();

    // ---- pass A: planes 0..2 (channels 0,4 | 1,3 | 8) ----
    {
        ull aF[3][4], aFp[3][4], aG[3][4], aGp[3][4];
        #pragma unroll
        for (int p = 0; p < 3; p++)
            #pragma unroll
            for (int j = 0; j < 4; j++) { aF[p][j] = 0; aFp[p][j] = 0; aG[p][j] = 0; aGp[p][j] = 0; }

        if (fitF) walk<3, true >(sS, 0, sCF,     g_runF, nrF, k0, warpKmax, aF, aFp);
        else      walk<3, false>(sS, 0, g_coefF, g_runF, nrF, k0, warpKmax, aF, aFp);
        if (fitG) walk<3, true >(sS, 0, sCG,     g_runG, nrG, k0, warpKmax, aG, aGp);
        else      walk<3, false>(sS, 0, g_coefG, g_runG, nrG, k0, warpKmax, aG, aGp);

        combine_write<3>(sOut, tid * 4, 0, aF, aFp, aG, aGp);
    }

    // ---- pass B: planes 3..4 (channels 2,6 | 5,7) ----
    {
        ull aF[2][4], aFp[2][4], aG[2][4], aGp[2][4];
        #pragma unroll
        for (int p = 0; p < 2; p++)
            #pragma unroll
            for (int j = 0; j < 4; j++) { aF[p][j] = 0; aFp[p][j] = 0; aG[p][j] = 0; aGp[p][j] = 0; }

        if (fitF) walk<2, true >(sS, 3, sCF,     g_runF, nrF, k0, warpKmax, aF, aFp);
        else      walk<2, false>(sS, 3, g_coefF, g_runF, nrF, k0, warpKmax, aF, aFp);
        if (fitG) walk<2, true >(sS, 3, sCG,     g_runG, nrG, k0, warpKmax, aG, aGp);
        else      walk<2, false>(sS, 3, g_coefG, g_runG, nrG, k0, warpKmax, aG, aGp);

        combine_write<2>(sOut, tid * 4, 3, aF, aFp, aG, aGp);
    }

    __syncthreads();
    float4* o4 = (float4*)(out + ((size_t)b * T + (size_t)kb) * 9);
    const float4* s4 = (const float4*)sOut;
    #pragma unroll
    for (int i = tid; i < 1024 * 9 / 4; i += 256) o4[i] = s4[i];
}

// ---------------- launch ----------------
extern "C" void kernel_launch(void* const* d_in, const int* in_sizes, int n_in,
                              void* d_out, int out_size) {
    (void)in_sizes; (void)n_in; (void)out_size;
    const float* x  = (const float*)d_in[0];
    const float* A1 = (const float*)d_in[1];
    const float* A2 = (const float*)d_in[2];
    FParams p;
    for (int f = 0; f < 4; f++) {
        p.W1[f] = (const float*)d_in[3 + 4 * f + 0];
        p.b1[f] = (const float*)d_in[3 + 4 * f + 1];
        p.W2[f] = (const float*)d_in[3 + 4 * f + 2];
        p.b2[f] = (const float*)d_in[3 + 4 * f + 3];
    }

    const int SM1 = 4 * T * 4 + 2 * T * 4;  // 98304 (filters block); pathdev uses 41984
    cudaFuncSetAttribute(k_main, cudaFuncAttributeMaxDynamicSharedMemorySize, SM1);
    k_main<<<BS + 1, 256, SM1>>>(x, A1, A2, p);

    const int SM2 = 5 * T * 8 + 2 * CAPC * 8 + 1024 * 9 * 4;  // 163840+16384+36864 = 217088
    cudaFuncSetAttribute(k_final, cudaFuncAttributeMaxDynamicSharedMemorySize, SM2);
    k_final<<<dim3(4, BS), 256, SM2>>>((float*)d_out);
}

// round 5
// speedup vs baseline: 1.0936x; 1.0936x over previous
#include <cuda_runtime.h>
#include <math.h>

#define T 4096
#define BS 128
#define CAPC 1024           // per-list shared coef cache (float2)
#define SUBP (T / 4)        // 1024: subplane length for mod-4 swizzle

typedef unsigned long long ull;

// swizzled row index within a plane: rows with equal (r mod 4) are contiguous
__host__ __device__ __forceinline__ int sw_idx(int r) {
    return ((r & 3) << 10) | (r >> 2);
}

// ---------------- device scratch ----------------
__device__ float2 g_S2[(size_t)BS * 5 * T];   // cumsum planes (b, plane, swizzled t)
__device__ float2 g_coefF[T + 8];             // dense tap coefs (df, dfp), run-ordered
__device__ float2 g_coefG[T + 8];
__device__ int4   g_runF[2052];               // (m0, len, coefBase, 0)
__device__ int4   g_runG[2052];
__device__ int    g_nF, g_nG, g_nrunF, g_nrunG;

struct FParams {
    const float* W1[4];
    const float* b1[4];
    const float* W2[4];
    const float* b2[4];
};

// ---------------- math helpers ----------------
__device__ __forceinline__ void make_E(float z0, float z1,
                                       float a1x, float a1y, float a1z,
                                       float a2x, float a2y, float a2z,
                                       float e[9]) {
    float wx = a1x * z0 + a2x * z1;
    float wy = a1y * z0 + a2y * z1;
    float wz = a1z * z0 + a2z * z1;
    float th2 = wx * wx + wy * wy + wz * wz;
    float s, c, c2;
    if (th2 > 1e-6f) {
        float th = sqrtf(th2);
        float sn, cn;
        sincosf(th, &sn, &cn);
        s = sn / th;
        c = cn;
        c2 = (1.f - cn) / th2;
    } else {
        s = 1.f - th2 * (1.f / 6.f);
        c = 1.f - th2 * 0.5f;
        c2 = 0.5f - th2 * (1.f / 24.f);
    }
    e[0] = c + c2 * wx * wx;      e[1] = c2 * wx * wy - s * wz; e[2] = c2 * wx * wz + s * wy;
    e[3] = c2 * wy * wx + s * wz; e[4] = c + c2 * wy * wy;      e[5] = c2 * wy * wz - s * wx;
    e[6] = c2 * wz * wx - s * wy; e[7] = c2 * wz * wy + s * wx; e[8] = c + c2 * wz * wz;
}

__device__ __forceinline__ void mul_right(float X[9], const float e[9]) {
    #pragma unroll
    for (int r = 0; r < 3; r++) {
        float x0 = X[r * 3], x1 = X[r * 3 + 1], x2 = X[r * 3 + 2];
        X[r * 3 + 0] = x0 * e[0] + x1 * e[3] + x2 * e[6];
        X[r * 3 + 1] = x0 * e[1] + x1 * e[4] + x2 * e[7];
        X[r * 3 + 2] = x0 * e[2] + x1 * e[5] + x2 * e[8];
    }
}

__device__ __forceinline__ void mul_left(float X[9], const float L[9]) {
    #pragma unroll
    for (int cc = 0; cc < 3; cc++) {
        float x0 = X[cc], x1 = X[3 + cc], x2 = X[6 + cc];
        X[cc]     = L[0] * x0 + L[1] * x1 + L[2] * x2;
        X[3 + cc] = L[3] * x0 + L[4] * x1 + L[5] * x2;
        X[6 + cc] = L[6] * x0 + L[7] * x1 + L[8] * x2;
    }
}

// ---------------- K_main: filters/runs block (bid==BS) + pathdev blocks ----------------
__device__ void build_runs(const int* tapm, int cnt, int4* runs, int* nrun_out) {
    int nr = 0, i = 0;
    while (i < cnt) {
        int m0 = tapm[i];
        int j = i + 1;
        while (j < cnt && tapm[j] == tapm[j - 1] + 1) j++;
        runs[nr] = make_int4(m0, j - i, i, 0);
        nr++;
        i = j;
    }
    runs[nr] = make_int4(0x7fffffff, 0, 0, 0);  // sentinel
    *nrun_out = nr;
}

__global__ void __launch_bounds__(256) k_main(const float* __restrict__ x_data,
                                              const float* __restrict__ A1,
                                              const float* __restrict__ A2,
                                              FParams p) {
    extern __shared__ float smem[];
    int tid = threadIdx.x;

    if (blockIdx.x == BS) {
        float* sh = smem;                         // [4][T]
        int* tapmF = (int*)(smem + 4 * T);        // [T]
        int* tapmG = tapmF + T;                   // [T]
        for (int idx = tid; idx < 4 * T; idx += 256) {
            int f = idx >> 12;
            int i = idx & (T - 1);
            float tt = (f < 2) ? (float)(T - 1 - i) : (float)i;  // f, fp reversed
            const float* W1 = p.W1[f];
            const float* b1 = p.b1[f];
            const float* W2 = p.W2[f];
            float acc = p.b2[f][0];
            #pragma unroll
            for (int u = 0; u < 5; u++)
                acc += W2[u] * tanhf(W1[u] * tt + b1[u]);
            sh[f * T + i] = acc;
        }
        __syncthreads();
        int wid = tid >> 5, lane = tid & 31;
        if (wid < 2) {
            int fa = wid * 2, fb = fa + 1;
            float2* cdst = wid ? g_coefG : g_coefF;
            int* mdst = wid ? tapmG : tapmF;
            int cnt = 0;
            for (int base = 0; base < T; base += 32) {
                int m = base + lane;
                float da = (m == 0) ? sh[fa * T] : sh[fa * T + m] - sh[fa * T + m - 1];
                float db = (m == 0) ? sh[fb * T] : sh[fb * T + m] - sh[fb * T + m - 1];
                int act = (da != 0.f) || (db != 0.f);
                unsigned mask = __ballot_sync(0xffffffffu, act);
                if (act) {
                    int pos = cnt + __popc(mask & ((1u << lane) - 1u));
                    cdst[pos] = make_float2(da, db);
                    mdst[pos] = m;
                }
                cnt += __popc(mask);
            }
            if (lane == 0) {
                if (wid == 0) g_nF = cnt; else g_nG = cnt;
            }
        }
        __syncthreads();
        if (tid == 0)  build_runs(tapmF, g_nF, g_runF, &g_nrunF);
        if (tid == 32) build_runs(tapmG, g_nG, g_runG, &g_nrunG);
        return;
    }

    // ---- pathdev block ----
    float* sx  = smem;          // 8192 floats
    float* smf = smem + 8192;   // 256*9 floats
    int b = blockIdx.x;

    {
        const float4* src = (const float4*)(x_data + (size_t)b * T * 2);
        float4* dst = (float4*)sx;
        #pragma unroll
        for (int i = tid; i < T * 2 / 4; i += 256) dst[i] = src[i];
    }

    float a1x = A1[7] - A1[5], a1y = A1[2] - A1[6], a1z = A1[3] - A1[1];
    float a2x = A2[7] - A2[5], a2y = A2[2] - A2[6], a2z = A2[3] - A2[1];
    __syncthreads();

    const int C = T / 256;  // 16
    int t0 = tid * C;

    float P[9] = {1, 0, 0, 0, 1, 0, 0, 0, 1};
    float CS[9] = {0, 0, 0, 0, 0, 0, 0, 0, 0};
    for (int i = 0; i < C; i++) {
        int t = t0 + i;
        if (t > 0) {
            float e[9];
            make_E(sx[2 * t], sx[2 * t + 1], a1x, a1y, a1z, a2x, a2y, a2z, e);
            mul_right(P, e);
        }
        #pragma unroll
        for (int d = 0; d < 9; d++) CS[d] += P[d];
    }

    float Pw[9];
    #pragma unroll
    for (int d = 0; d < 9; d++) { Pw[d] = P[d]; smf[tid * 9 + d] = P[d]; }
    for (int off = 1; off < 256; off <<= 1) {
        __syncthreads();
        float L[9];
        int has = tid >= off;
        if (has) {
            #pragma unroll
            for (int d = 0; d < 9; d++) L[d] = smf[(tid - off) * 9 + d];
        }
        __syncthreads();
        if (has) {
            mul_left(Pw, L);
            #pragma unroll
            for (int d = 0; d < 9; d++) smf[tid * 9 + d] = Pw[d];
        }
    }
    __syncthreads();
    float PM[9];
    if (tid > 0) {
        #pragma unroll
        for (int d = 0; d < 9; d++) PM[d] = smf[(tid - 1) * 9 + d];
    } else {
        #pragma unroll
        for (int d = 0; d < 9; d++) PM[d] = (d == 0 || d == 4 || d == 8) ? 1.f : 0.f;
    }
    __syncthreads();

    float CSg[9];
    #pragma unroll
    for (int i = 0; i < 3; i++)
        #pragma unroll
        for (int j = 0; j < 3; j++)
            CSg[3 * i + j] = PM[3 * i + 0] * CS[0 + j] + PM[3 * i + 1] * CS[3 + j] + PM[3 * i + 2] * CS[6 + j];

    float Aw[9];
    #pragma unroll
    for (int d = 0; d < 9; d++) { Aw[d] = CSg[d]; smf[tid * 9 + d] = CSg[d]; }
    for (int off = 1; off < 256; off <<= 1) {
        __syncthreads();
        float L[9];
        int has = tid >= off;
        if (has) {
            #pragma unroll
            for (int d = 0; d < 9; d++) L[d] = smf[(tid - off) * 9 + d];
        }
        __syncthreads();
        if (has) {
            #pragma unroll
            for (int d = 0; d < 9; d++) { Aw[d] += L[d]; smf[tid * 9 + d] = Aw[d]; }
        }
    }
    __syncthreads();
    float PS[9];
    if (tid > 0) {
        #pragma unroll
        for (int d = 0; d < 9; d++) PS[d] = smf[(tid - 1) * 9 + d];
    } else {
        #pragma unroll
        for (int d = 0; d < 9; d++) PS[d] = 0.f;
    }

    float X[9];
    #pragma unroll
    for (int d = 0; d < 9; d++) X[d] = PM[d];
    float2* Sb = g_S2 + (size_t)b * 5 * T;
    for (int i = 0; i < C; i++) {
        int t = t0 + i;
        if (t > 0) {
            float e[9];
            make_E(sx[2 * t], sx[2 * t + 1], a1x, a1y, a1z, a2x, a2y, a2z, e);
            mul_right(X, e);
        }
        #pragma unroll
        for (int d = 0; d < 9; d++) PS[d] += X[d];
        int si = sw_idx(t);
        // transpose-closed pairing: (0,4) (1,3) (8,-) (2,6) (5,7)
        Sb[0 * T + si] = make_float2(PS[0], PS[4]);
        Sb[1 * T + si] = make_float2(PS[1], PS[3]);
        Sb[2 * T + si] = make_float2(PS[8], 0.f);
        Sb[3 * T + si] = make_float2(PS[2], PS[6]);
        Sb[4 * T + si] = make_float2(PS[5], PS[7]);
    }
}

// ---------------- K_final: sliding-window register FIR (swizzled smem) ----------------
__device__ __forceinline__ ull packf(float a) {
    ull r;
    asm("mov.b64 %0, {%1, %1};" : "=l"(r) : "f"(a));
    return r;
}
__device__ __forceinline__ ull f2bits(float2 v) {
    ull r;
    asm("mov.b64 %0, {%1, %2};" : "=l"(r) : "f"(v.x), "f"(v.y));
    return r;
}
__device__ __forceinline__ void fma2(ull& acc, ull a, ull b) {
    asm("fma.rn.f32x2 %0, %1, %2, %0;" : "+l"(acc) : "l"(a), "l"(b));
}
__device__ __forceinline__ void unpck(ull v, float& lo, float& hi) {
    asm("mov.b64 {%0, %1}, %2;" : "=f"(lo), "=f"(hi) : "l"(v));
}

template <int NP>
__device__ __forceinline__ void ld_guard(const float2* __restrict__ sS, int pb,
                                         int r, ull W[NP][4], int slot) {
    bool v = r >= 0;
    int rr = v ? r : 0;
    int off = sw_idx(rr);
    #pragma unroll
    for (int p = 0; p < NP; p++) {
        float2 d = sS[(pb + p) * T + off];
        W[p][slot] = v ? f2bits(d) : 0ULL;
    }
}

template <int NP, bool SH>
__device__ void walk(const float2* __restrict__ sS, int pb,
                     const float2* __restrict__ coefs,
                     const int4* __restrict__ runs, int nrun,
                     int k0, int warpKmax,
                     ull accA[NP][4], ull accB[NP][4]) {
    for (int ri = 0; ri < nrun; ri++) {
        int4 rn = __ldg(&runs[ri]);
        int m0 = rn.x;
        if (m0 > warpKmax) break;
        int L = min(rn.y, warpKmax - m0 + 1);
        const float2* cc = coefs + rn.z;

        ull W[NP][4];
        #pragma unroll
        for (int j = 0; j < 4; j++)
            ld_guard<NP>(sS, pb, k0 + j - m0, W, j);

        int i = 0;
        for (; i + 4 <= L; i += 4) {
            #pragma unroll
            for (int u = 0; u < 4; u++) {
                float2 cf = SH ? cc[i + u] : __ldg(&cc[i + u]);
                ull cy = packf(cf.x), cz = packf(cf.y);
                #pragma unroll
                for (int p = 0; p < NP; p++)
                    #pragma unroll
                    for (int j = 0; j < 4; j++) {
                        ull w = W[p][(j - u) & 3];
                        fma2(accA[p][j], w, cy);
                        fma2(accB[p][j], w, cz);
                    }
                ld_guard<NP>(sS, pb, k0 - m0 - (i + u) - 1, W, (3 - u) & 3);
            }
        }
        #pragma unroll
        for (int u = 0; u < 3; u++) {
            if (i + u < L) {
                float2 cf = SH ? cc[i + u] : __ldg(&cc[i + u]);
                ull cy = packf(cf.x), cz = packf(cf.y);
                #pragma unroll
                for (int p = 0; p < NP; p++)
                    #pragma unroll
                    for (int j = 0; j < 4; j++) {
                        ull w = W[p][(j - u) & 3];
                        fma2(accA[p][j], w, cy);
                        fma2(accB[p][j], w, cz);
                    }
                ld_guard<NP>(sS, pb, k0 - m0 - (i + u) - 1, W, (3 - u) & 3);
            }
        }
    }
}

template <int NP>
__device__ __forceinline__ void combine_write(float* __restrict__ sOut, int lt0, int pb,
                                              ull aF[NP][4], ull aFp[NP][4],
                                              ull aG[NP][4], ull aGp[NP][4]) {
    const int  chx[5] = {0, 1, 8, 2, 5};
    const int  chy[5] = {4, 3, -1, 6, 7};
    const bool SW[5]  = {false, true, false, true, true};
    #pragma unroll
    for (int p = 0; p < NP; p++) {
        int P = pb + p;
        #pragma unroll
        for (int j = 0; j < 4; j++) {
            float fLo, fHi, pLo, pHi, gLo, gHi, qLo, qHi;
            unpck(aF[p][j],  fLo, fHi);
            unpck(aFp[p][j], pLo, pHi);
            unpck(aG[p][j],  gLo, gHi);
            unpck(aGp[p][j], qLo, qHi);
            float FL = SW[P] ? fHi : fLo, FH = SW[P] ? fLo : fHi;
            float PL = SW[P] ? pHi : pLo, PH = SW[P] ? pLo : pHi;
            int lt = lt0 + j;
            sOut[lt * 9 + chx[P]] = FL * gLo + PL * qLo;
            if (chy[P] >= 0)
                sOut[lt * 9 + chy[P]] = FH * gHi + PH * qHi;
        }
    }
}

__global__ void __launch_bounds__(256, 1) k_final(float* __restrict__ out) {
    extern __shared__ __align__(16) char smem_raw[];
    float2* sS   = (float2*)smem_raw;                 // 5*T float2 = 163840 B
    float2* sCF  = sS + 5 * T;                        // 8192 B
    float2* sCG  = sCF + CAPC;                        // 8192 B
    float*  sOut = (float*)(sCG + CAPC);              // 1024*9 floats = 36864 B

    int q = blockIdx.x, b = blockIdx.y, tid = threadIdx.x;
    int kb = q * 1024;
    int k0 = kb + tid * 4;
    int warpKmax = kb + ((tid >> 5) + 1) * 128 - 1;
    int nrows = kb + 1024;

    // stage S planes: swizzled layout — rows [0, nrows) occupy per-subplane
    // prefixes [s*SUBP, s*SUBP + nrows/4); each segment is contiguous.
    {
        const float2* src = g_S2 + (size_t)b * 5 * T;
        int cnt4 = nrows / 8;   // float4s per (plane, subplane) segment
        #pragma unroll
        for (int pp = 0; pp < 5; pp++)
            #pragma unroll
            for (int s = 0; s < 4; s++) {
                const float4* s4 = (const float4*)(src + pp * T + s * SUBP);
                float4* d4 = (float4*)(sS + pp * T + s * SUBP);
                for (int i = tid; i < cnt4; i += 256) d4[i] = s4[i];
            }
    }
    int nF = g_nF, nG = g_nG, nrF = g_nrunF, nrG = g_nrunG;
    bool fitF = nF <= CAPC, fitG = nG <= CAPC;
    if (fitF) for (int i = tid; i < nF; i += 256) sCF[i] = g_coefF[i];
    if (fitG) for (int i = tid; i < nG; i += 256) sCG[i] = g_coefG[i];
    __syncthreads();

    // ---- pass A: planes 0..2 (channels 0,4 | 1,3 | 8) ----
    {
        ull aF[3][4], aFp[3][4], aG[3][4], aGp[3][4];
        #pragma unroll
        for (int p = 0; p < 3; p++)
            #pragma unroll
            for (int j = 0; j < 4; j++) { aF[p][j] = 0; aFp[p][j] = 0; aG[p][j] = 0; aGp[p][j] = 0; }

        if (fitF) walk<3, true >(sS, 0, sCF,     g_runF, nrF, k0, warpKmax, aF, aFp);
        else      walk<3, false>(sS, 0, g_coefF, g_runF, nrF, k0, warpKmax, aF, aFp);
        if (fitG) walk<3, true >(sS, 0, sCG,     g_runG, nrG, k0, warpKmax, aG, aGp);
        else      walk<3, false>(sS, 0, g_coefG, g_runG, nrG, k0, warpKmax, aG, aGp);

        combine_write<3>(sOut, tid * 4, 0, aF, aFp, aG, aGp);
    }

    // ---- pass B: planes 3..4 (channels 2,6 | 5,7) ----
    {
        ull aF[2][4], aFp[2][4], aG[2][4], aGp[2][4];
        #pragma unroll
        for (int p = 0; p < 2; p++)
            #pragma unroll
            for (int j = 0; j < 4; j++) { aF[p][j] = 0; aFp[p][j] = 0; aG[p][j] = 0; aGp[p][j] = 0; }

        if (fitF) walk<2, true >(sS, 3, sCF,     g_runF, nrF, k0, warpKmax, aF, aFp);
        else      walk<2, false>(sS, 3, g_coefF, g_runF, nrF, k0, warpKmax, aF, aFp);
        if (fitG) walk<2, true >(sS, 3, sCG,     g_runG, nrG, k0, warpKmax, aG, aGp);
        else      walk<2, false>(sS, 3, g_coefG, g_runG, nrG, k0, warpKmax, aG, aGp);

        combine_write<2>(sOut, tid * 4, 3, aF, aFp, aG, aGp);
    }

    __syncthreads();
    float4* o4 = (float4*)(out + ((size_t)b * T + (size_t)kb) * 9);
    const float4* s4 = (const float4*)sOut;
    #pragma unroll
    for (int i = tid; i < 1024 * 9 / 4; i += 256) o4[i] = s4[i];
}

// ---------------- launch ----------------
extern "C" void kernel_launch(void* const* d_in, const int* in_sizes, int n_in,
                              void* d_out, int out_size) {
    (void)in_sizes; (void)n_in; (void)out_size;
    const float* x  = (const float*)d_in[0];
    const float* A1 = (const float*)d_in[1];
    const float* A2 = (const float*)d_in[2];
    FParams p;
    for (int f = 0; f < 4; f++) {
        p.W1[f] = (const float*)d_in[3 + 4 * f + 0];
        p.b1[f] = (const float*)d_in[3 + 4 * f + 1];
        p.W2[f] = (const float*)d_in[3 + 4 * f + 2];
        p.b2[f] = (const float*)d_in[3 + 4 * f + 3];
    }

    const int SM1 = 4 * T * 4 + 2 * T * 4;  // 98304 (filters block); pathdev uses 41984
    cudaFuncSetAttribute(k_main, cudaFuncAttributeMaxDynamicSharedMemorySize, SM1);
    k_main<<<BS + 1, 256, SM1>>>(x, A1, A2, p);

    const int SM2 = 5 * T * 8 + 2 * CAPC * 8 + 1024 * 9 * 4;  // 217088
    cudaFuncSetAttribute(k_final, cudaFuncAttributeMaxDynamicSharedMemorySize, SM2);
    k_final<<<dim3(4, BS), 256, SM2>>>((float*)d_out);
}

// round 6
// speedup vs baseline: 1.1821x; 1.0810x over previous
#include <cuda_runtime.h>
#include <math.h>

#define T 4096
#define BS 128
#define PT 4224            // padded rows per plane: T + 128 guard rows
#define SUBQ 1056          // PT/4, subplane length (mod-4 swizzle)
#define CAPC 1024          // coef cache entries (float4) per list
#define RCAP 512           // run cache entries per list

typedef unsigned long long ull;

// ---------------- device scratch ----------------
// swizzled padded planes: row t lives at (t&3)*SUBQ + (t>>2) + 32 within plane
__device__ float2 g_S2[(size_t)BS * 5 * PT];
__device__ float4 g_coefF[T + 8];             // (df, df, dfp, dfp), run-ordered
__device__ float4 g_coefG[T + 8];
__device__ int4   g_runF[2052];               // (m0, len, coefBase, 0)
__device__ int4   g_runG[2052];
__device__ int    g_nF, g_nG, g_nrunF, g_nrunG;

struct FParams {
    const float* W1[4];
    const float* b1[4];
    const float* W2[4];
    const float* b2[4];
};

// ---------------- math helpers ----------------
__device__ __forceinline__ void make_E(float z0, float z1,
                                       float a1x, float a1y, float a1z,
                                       float a2x, float a2y, float a2z,
                                       float e[9]) {
    float wx = a1x * z0 + a2x * z1;
    float wy = a1y * z0 + a2y * z1;
    float wz = a1z * z0 + a2z * z1;
    float th2 = wx * wx + wy * wy + wz * wz;
    float s, c, c2;
    if (th2 > 1e-6f) {
        float th = sqrtf(th2);
        float sn, cn;
        sincosf(th, &sn, &cn);
        s = sn / th;
        c = cn;
        c2 = (1.f - cn) / th2;
    } else {
        s = 1.f - th2 * (1.f / 6.f);
        c = 1.f - th2 * 0.5f;
        c2 = 0.5f - th2 * (1.f / 24.f);
    }
    e[0] = c + c2 * wx * wx;      e[1] = c2 * wx * wy - s * wz; e[2] = c2 * wx * wz + s * wy;
    e[3] = c2 * wy * wx + s * wz; e[4] = c + c2 * wy * wy;      e[5] = c2 * wy * wz - s * wx;
    e[6] = c2 * wz * wx - s * wy; e[7] = c2 * wz * wy + s * wx; e[8] = c + c2 * wz * wz;
}

__device__ __forceinline__ void mul_right(float X[9], const float e[9]) {
    #pragma unroll
    for (int r = 0; r < 3; r++) {
        float x0 = X[r * 3], x1 = X[r * 3 + 1], x2 = X[r * 3 + 2];
        X[r * 3 + 0] = x0 * e[0] + x1 * e[3] + x2 * e[6];
        X[r * 3 + 1] = x0 * e[1] + x1 * e[4] + x2 * e[7];
        X[r * 3 + 2] = x0 * e[2] + x1 * e[5] + x2 * e[8];
    }
}

__device__ __forceinline__ void mul_left(float X[9], const float L[9]) {
    #pragma unroll
    for (int cc = 0; cc < 3; cc++) {
        float x0 = X[cc], x1 = X[3 + cc], x2 = X[6 + cc];
        X[cc]     = L[0] * x0 + L[1] * x1 + L[2] * x2;
        X[3 + cc] = L[3] * x0 + L[4] * x1 + L[5] * x2;
        X[6 + cc] = L[6] * x0 + L[7] * x1 + L[8] * x2;
    }
}

// ---------------- K_main: filters/runs block (bid==BS) + pathdev blocks ----------------
__device__ void build_runs(const int* tapm, int cnt, int4* runs, int* nrun_out) {
    int nr = 0, i = 0;
    while (i < cnt) {
        int m0 = tapm[i];
        int j = i + 1;
        while (j < cnt && tapm[j] == tapm[j - 1] + 1) j++;
        runs[nr] = make_int4(m0, j - i, i, 0);
        nr++;
        i = j;
    }
    runs[nr] = make_int4(0x7fffffff, 0, 0, 0);  // sentinel
    *nrun_out = nr;
}

__global__ void __launch_bounds__(256) k_main(const float* __restrict__ x_data,
                                              const float* __restrict__ A1,
                                              const float* __restrict__ A2,
                                              FParams p) {
    extern __shared__ float smem[];
    int tid = threadIdx.x;

    if (blockIdx.x == BS) {
        float* sh = smem;                         // [4][T]
        int* tapmF = (int*)(smem + 4 * T);        // [T]
        int* tapmG = tapmF + T;                   // [T]
        for (int idx = tid; idx < 4 * T; idx += 256) {
            int f = idx >> 12;
            int i = idx & (T - 1);
            float tt = (f < 2) ? (float)(T - 1 - i) : (float)i;  // f, fp reversed
            const float* W1 = p.W1[f];
            const float* b1 = p.b1[f];
            const float* W2 = p.W2[f];
            float acc = p.b2[f][0];
            #pragma unroll
            for (int u = 0; u < 5; u++)
                acc += W2[u] * tanhf(W1[u] * tt + b1[u]);
            sh[f * T + i] = acc;
        }
        __syncthreads();
        int wid = tid >> 5, lane = tid & 31;
        if (wid < 2) {
            int fa = wid * 2, fb = fa + 1;
            float4* cdst = wid ? g_coefG : g_coefF;
            int* mdst = wid ? tapmG : tapmF;
            int cnt = 0;
            for (int base = 0; base < T; base += 32) {
                int m = base + lane;
                float da = (m == 0) ? sh[fa * T] : sh[fa * T + m] - sh[fa * T + m - 1];
                float db = (m == 0) ? sh[fb * T] : sh[fb * T + m] - sh[fb * T + m - 1];
                int act = (da != 0.f) || (db != 0.f);
                unsigned mask = __ballot_sync(0xffffffffu, act);
                if (act) {
                    int pos = cnt + __popc(mask & ((1u << lane) - 1u));
                    cdst[pos] = make_float4(da, da, db, db);  // pre-broadcast
                    mdst[pos] = m;
                }
                cnt += __popc(mask);
            }
            if (lane == 0) {
                if (wid == 0) g_nF = cnt; else g_nG = cnt;
            }
        }
        __syncthreads();
        if (tid == 0)  build_runs(tapmF, g_nF, g_runF, &g_nrunF);
        if (tid == 32) build_runs(tapmG, g_nG, g_runG, &g_nrunG);
        return;
    }

    // ---- pathdev block ----
    float* sx  = smem;          // 8192 floats
    float* smf = smem + 8192;   // 256*9 floats
    int b = blockIdx.x;

    {
        const float4* src = (const float4*)(x_data + (size_t)b * T * 2);
        float4* dst = (float4*)sx;
        #pragma unroll
        for (int i = tid; i < T * 2 / 4; i += 256) dst[i] = src[i];
    }

    float a1x = A1[7] - A1[5], a1y = A1[2] - A1[6], a1z = A1[3] - A1[1];
    float a2x = A2[7] - A2[5], a2y = A2[2] - A2[6], a2z = A2[3] - A2[1];
    __syncthreads();

    const int C = T / 256;  // 16
    int t0 = tid * C;

    float P[9] = {1, 0, 0, 0, 1, 0, 0, 0, 1};
    float CS[9] = {0, 0, 0, 0, 0, 0, 0, 0, 0};
    for (int i = 0; i < C; i++) {
        int t = t0 + i;
        if (t > 0) {
            float e[9];
            make_E(sx[2 * t], sx[2 * t + 1], a1x, a1y, a1z, a2x, a2y, a2z, e);
            mul_right(P, e);
        }
        #pragma unroll
        for (int d = 0; d < 9; d++) CS[d] += P[d];
    }

    float Pw[9];
    #pragma unroll
    for (int d = 0; d < 9; d++) { Pw[d] = P[d]; smf[tid * 9 + d] = P[d]; }
    for (int off = 1; off < 256; off <<= 1) {
        __syncthreads();
        float L[9];
        int has = tid >= off;
        if (has) {
            #pragma unroll
            for (int d = 0; d < 9; d++) L[d] = smf[(tid - off) * 9 + d];
        }
        __syncthreads();
        if (has) {
            mul_left(Pw, L);
            #pragma unroll
            for (int d = 0; d < 9; d++) smf[tid * 9 + d] = Pw[d];
        }
    }
    __syncthreads();
    float PM[9];
    if (tid > 0) {
        #pragma unroll
        for (int d = 0; d < 9; d++) PM[d] = smf[(tid - 1) * 9 + d];
    } else {
        #pragma unroll
        for (int d = 0; d < 9; d++) PM[d] = (d == 0 || d == 4 || d == 8) ? 1.f : 0.f;
    }
    __syncthreads();

    float CSg[9];
    #pragma unroll
    for (int i = 0; i < 3; i++)
        #pragma unroll
        for (int j = 0; j < 3; j++)
            CSg[3 * i + j] = PM[3 * i + 0] * CS[0 + j] + PM[3 * i + 1] * CS[3 + j] + PM[3 * i + 2] * CS[6 + j];

    float Aw[9];
    #pragma unroll
    for (int d = 0; d < 9; d++) { Aw[d] = CSg[d]; smf[tid * 9 + d] = CSg[d]; }
    for (int off = 1; off < 256; off <<= 1) {
        __syncthreads();
        float L[9];
        int has = tid >= off;
        if (has) {
            #pragma unroll
            for (int d = 0; d < 9; d++) L[d] = smf[(tid - off) * 9 + d];
        }
        __syncthreads();
        if (has) {
            #pragma unroll
            for (int d = 0; d < 9; d++) { Aw[d] += L[d]; smf[tid * 9 + d] = Aw[d]; }
        }
    }
    __syncthreads();
    float PS[9];
    if (tid > 0) {
        #pragma unroll
        for (int d = 0; d < 9; d++) PS[d] = smf[(tid - 1) * 9 + d];
    } else {
        #pragma unroll
        for (int d = 0; d < 9; d++) PS[d] = 0.f;
    }

    float X[9];
    #pragma unroll
    for (int d = 0; d < 9; d++) X[d] = PM[d];
    float2* Sb = g_S2 + (size_t)b * 5 * PT;
    for (int i = 0; i < C; i++) {
        int t = t0 + i;
        if (t > 0) {
            float e[9];
            make_E(sx[2 * t], sx[2 * t + 1], a1x, a1y, a1z, a2x, a2y, a2z, e);
            mul_right(X, e);
        }
        #pragma unroll
        for (int d = 0; d < 9; d++) PS[d] += X[d];
        int si = ((t & 3) * SUBQ) + (t >> 2) + 32;   // swizzled + pad offset
        // transpose-closed pairing: (0,4) (1,3) (8,-) (2,6) (5,7)
        Sb[0 * PT + si] = make_float2(PS[0], PS[4]);
        Sb[1 * PT + si] = make_float2(PS[1], PS[3]);
        Sb[2 * PT + si] = make_float2(PS[8], 0.f);
        Sb[3 * PT + si] = make_float2(PS[2], PS[6]);
        Sb[4 * PT + si] = make_float2(PS[5], PS[7]);
    }
}

// ---------------- K_final: guard-free sliding-window FIR ----------------
__device__ __forceinline__ ull f2pair(float a, float b) {
    ull r;
    asm("mov.b64 %0, {%1, %2};" : "=l"(r) : "f"(a), "f"(b));
    return r;
}
__device__ __forceinline__ ull f2bits(float2 v) {
    ull r;
    asm("mov.b64 %0, {%1, %2};" : "=l"(r) : "f"(v.x), "f"(v.y));
    return r;
}
__device__ __forceinline__ void fma2(ull& acc, ull a, ull b) {
    asm("fma.rn.f32x2 %0, %1, %2, %0;" : "+l"(acc) : "l"(a), "l"(b));
}
__device__ __forceinline__ void unpck(ull v, float& lo, float& hi) {
    asm("mov.b64 {%0, %1}, %2;" : "=f"(lo), "=f"(hi) : "l"(v));
}

template <int NP, bool SHC, bool SHR>
__device__ void walk(const float2* __restrict__ sSb,       // base of first plane
                     const float4* __restrict__ coefs,
                     const int4* __restrict__ runs, int nrun,
                     int k0, int warpKmax,
                     ull accA[NP][4], ull accB[NP][4]) {
    for (int ri = 0; ri < nrun; ri++) {
        int4 rn = SHR ? runs[ri] : __ldg(&runs[ri]);
        int m0 = rn.x;
        if (m0 > warpKmax) break;
        int L = min(rn.y, warpKmax - m0 + 1);
        const float4* cc = coefs + rn.z;

        int rtop = k0 + 128 - m0;   // padded row' of window slot j=0

        ull W[NP][4];
        #pragma unroll
        for (int j = 0; j < 4; j++) {
            int rp = rtop + j;
            int off = ((rp & 3) * SUBQ) + (rp >> 2);
            #pragma unroll
            for (int p = 0; p < NP; p++)
                W[p][j] = f2bits(sSb[p * PT + off]);
        }
        // refill offsets: refill in group i at sub-step u reads row' rtop-1-(i+u);
        // i += 4 per group => same subplane, entry index decrements by 1.
        int offu[4];
        #pragma unroll
        for (int u = 0; u < 4; u++) {
            int rp = rtop - 1 - u;
            offu[u] = ((rp & 3) * SUBQ) + (rp >> 2);
        }

        int i = 0;
        for (; i + 4 <= L; i += 4) {
            #pragma unroll
            for (int u = 0; u < 4; u++) {
                float4 cf = SHC ? cc[i + u] : __ldg(&cc[i + u]);
                ull cy = f2pair(cf.x, cf.y);
                ull cz = f2pair(cf.z, cf.w);
                #pragma unroll
                for (int p = 0; p < NP; p++)
                    #pragma unroll
                    for (int j = 0; j < 4; j++) {
                        ull w = W[p][(j - u) & 3];
                        fma2(accA[p][j], w, cy);
                        fma2(accB[p][j], w, cz);
                    }
                // unguarded refill (zero-padded planes make it always legal)
                #pragma unroll
                for (int p = 0; p < NP; p++)
                    W[p][(3 - u) & 3] = f2bits(sSb[p * PT + offu[u]]);
                offu[u] -= 1;
            }
        }
        // tail: FMAs only, no refills (window dies at run end)
        #pragma unroll
        for (int u = 0; u < 3; u++) {
            if (i + u < L) {
                float4 cf = SHC ? cc[i + u] : __ldg(&cc[i + u]);
                ull cy = f2pair(cf.x, cf.y);
                ull cz = f2pair(cf.z, cf.w);
                #pragma unroll
                for (int p = 0; p < NP; p++)
                    #pragma unroll
                    for (int j = 0; j < 4; j++) {
                        ull w = W[p][(j - u) & 3];
                        fma2(accA[p][j], w, cy);
                        fma2(accB[p][j], w, cz);
                    }
            }
        }
    }
}

__global__ void __launch_bounds__(256, 1) k_final(float* __restrict__ out) {
    extern __shared__ __align__(16) char smem_raw[];
    float2* sS  = (float2*)smem_raw;                  // 5*PT float2 = 168960 B
    float4* sCF = (float4*)(sS + 5 * PT);             // 16384 B
    float4* sCG = sCF + CAPC;                         // 16384 B
    int4*   sRF = (int4*)(sCG + CAPC);                // 8192 B
    int4*   sRG = sRF + RCAP;                         // 8192 B

    int q = blockIdx.x, b = blockIdx.y, tid = threadIdx.x;
    int kb = q * 1024;
    int k0 = kb + tid * 4;
    int warpKmax = kb + ((tid >> 5) + 1) * 128 - 1;
    int nrows = kb + 1024;

    // stage S planes (data regions) + zero the 128 pad rows per plane
    {
        const float2* src = g_S2 + (size_t)b * 5 * PT;
        int cnt4 = nrows >> 3;   // float4s per (plane, subplane) data segment
        #pragma unroll
        for (int pp = 0; pp < 5; pp++)
            #pragma unroll
            for (int s = 0; s < 4; s++) {
                const float4* s4 = (const float4*)(src + pp * PT + s * SUBQ + 32);
                float4* d4 = (float4*)(sS + pp * PT + s * SUBQ + 32);
                for (int i = tid; i < cnt4; i += 256) d4[i] = s4[i];
            }
        for (int i = tid; i < 5 * 4 * 32; i += 256) {
            int pl = i >> 7, r = i & 127, s = r >> 5, e = r & 31;
            sS[pl * PT + s * SUBQ + e] = make_float2(0.f, 0.f);
        }
    }
    int nF = g_nF, nG = g_nG, nrF = g_nrunF, nrG = g_nrunG;
    bool fitCF = nF <= CAPC, fitCG = nG <= CAPC;
    bool fitRF = nrF <= RCAP, fitRG = nrG <= RCAP;
    if (fitCF) for (int i = tid; i < nF; i += 256) sCF[i] = g_coefF[i];
    if (fitCG) for (int i = tid; i < nG; i += 256) sCG[i] = g_coefG[i];
    if (fitRF) for (int i = tid; i < nrF; i += 256) sRF[i] = g_runF[i];
    if (fitRG) for (int i = tid; i < nrG; i += 256) sRG[i] = g_runG[i];
    __syncthreads();

    float* po = out + ((size_t)b * T + (size_t)k0) * 9;

    // ---- pass A: planes 0..2 (channels 0,4 | 1,3 | 8) ----
    {
        ull aF[3][4], aFp[3][4], aG[3][4], aGp[3][4];
        #pragma unroll
        for (int p = 0; p < 3; p++)
            #pragma unroll
            for (int j = 0; j < 4; j++) { aF[p][j] = 0; aFp[p][j] = 0; aG[p][j] = 0; aGp[p][j] = 0; }

        if (fitCF && fitRF)      walk<3, true,  true >(sS, sCF,     sRF,    nrF, k0, warpKmax, aF, aFp);
        else if (fitCF)          walk<3, true,  false>(sS, sCF,     g_runF, nrF, k0, warpKmax, aF, aFp);
        else                     walk<3, false, false>(sS, g_coefF, g_runF, nrF, k0, warpKmax, aF, aFp);
        if (fitCG && fitRG)      walk<3, true,  true >(sS, sCG,     sRG,    nrG, k0, warpKmax, aG, aGp);
        else if (fitCG)          walk<3, true,  false>(sS, sCG,     g_runG, nrG, k0, warpKmax, aG, aGp);
        else                     walk<3, false, false>(sS, g_coefG, g_runG, nrG, k0, warpKmax, aG, aGp);

        // plane p channels: p0 -> (0,4) no swap; p1 -> (1,3) swap; p2 -> (8) no swap
        #pragma unroll
        for (int j = 0; j < 4; j++) {
            float fLo, fHi, pLo, pHi, gLo, gHi, qLo, qHi;
            unpck(aF[0][j], fLo, fHi);  unpck(aFp[0][j], pLo, pHi);
            unpck(aG[0][j], gLo, gHi);  unpck(aGp[0][j], qLo, qHi);
            po[j * 9 + 0] = fLo * gLo + pLo * qLo;
            po[j * 9 + 4] = fHi * gHi + pHi * qHi;
            unpck(aF[1][j], fLo, fHi);  unpck(aFp[1][j], pLo, pHi);
            unpck(aG[1][j], gLo, gHi);  unpck(aGp[1][j], qLo, qHi);
            po[j * 9 + 1] = fHi * gLo + pHi * qLo;   // swap for F terms
            po[j * 9 + 3] = fLo * gHi + pLo * qHi;
            unpck(aF[2][j], fLo, fHi);  unpck(aFp[2][j], pLo, pHi);
            unpck(aG[2][j], gLo, gHi);  unpck(aGp[2][j], qLo, qHi);
            po[j * 9 + 8] = fLo * gLo + pLo * qLo;
        }
    }

    // ---- pass B: planes 3..4 (channels 2,6 | 5,7), both swapped for F ----
    {
        ull aF[2][4], aFp[2][4], aG[2][4], aGp[2][4];
        #pragma unroll
        for (int p = 0; p < 2; p++)
            #pragma unroll
            for (int j = 0; j < 4; j++) { aF[p][j] = 0; aFp[p][j] = 0; aG[p][j] = 0; aGp[p][j] = 0; }

        const float2* sSb = sS + 3 * PT;
        if (fitCF && fitRF)      walk<2, true,  true >(sSb, sCF,     sRF,    nrF, k0, warpKmax, aF, aFp);
        else if (fitCF)          walk<2, true,  false>(sSb, sCF,     g_runF, nrF, k0, warpKmax, aF, aFp);
        else                     walk<2, false, false>(sSb, g_coefF, g_runF, nrF, k0, warpKmax, aF, aFp);
        if (fitCG && fitRG)      walk<2, true,  true >(sSb, sCG,     sRG,    nrG, k0, warpKmax, aG, aGp);
        else if (fitCG)          walk<2, true,  false>(sSb, sCG,     g_runG, nrG, k0, warpKmax, aG, aGp);
        else                     walk<2, false, false>(sSb, g_coefG, g_runG, nrG, k0, warpKmax, aG, aGp);

        #pragma unroll
        for (int j = 0; j < 4; j++) {
            float fLo, fHi, pLo, pHi, gLo, gHi, qLo, qHi;
            unpck(aF[0][j], fLo, fHi);  unpck(aFp[0][j], pLo, pHi);
            unpck(aG[0][j], gLo, gHi);  unpck(aGp[0][j], qLo, qHi);
            po[j * 9 + 2] = fHi * gLo + pHi * qLo;   // (2,6) swap
            po[j * 9 + 6] = fLo * gHi + pLo * qHi;
            unpck(aF[1][j], fLo, fHi);  unpck(aFp[1][j], pLo, pHi);
            unpck(aG[1][j], gLo, gHi);  unpck(aGp[1][j], qLo, qHi);
            po[j * 9 + 5] = fHi * gLo + pHi * qLo;   // (5,7) swap
            po[j * 9 + 7] = fLo * gHi + pLo * qHi;
        }
    }
}

// ---------------- launch ----------------
extern "C" void kernel_launch(void* const* d_in, const int* in_sizes, int n_in,
                              void* d_out, int out_size) {
    (void)in_sizes; (void)n_in; (void)out_size;
    const float* x  = (const float*)d_in[0];
    const float* A1 = (const float*)d_in[1];
    const float* A2 = (const float*)d_in[2];
    FParams p;
    for (int f = 0; f < 4; f++) {
        p.W1[f] = (const float*)d_in[3 + 4 * f + 0];
        p.b1[f] = (const float*)d_in[3 + 4 * f + 1];
        p.W2[f] = (const float*)d_in[3 + 4 * f + 2];
        p.b2[f] = (const float*)d_in[3 + 4 * f + 3];
    }

    const int SM1 = 4 * T * 4 + 2 * T * 4;  // 98304 (filters block); pathdev uses 41984
    cudaFuncSetAttribute(k_main, cudaFuncAttributeMaxDynamicSharedMemorySize, SM1);
    k_main<<<BS + 1, 256, SM1>>>(x, A1, A2, p);

    const int SM2 = 5 * PT * 8 + 2 * CAPC * 16 + 2 * RCAP * 16;  // 168960+32768+16384 = 218112
    cudaFuncSetAttribute(k_final, cudaFuncAttributeMaxDynamicSharedMemorySize, SM2);
    k_final<<<dim3(4, BS), 256, SM2>>>((float*)d_out);
}

// round 7
// speedup vs baseline: 1.3808x; 1.1680x over previous
#include <cuda_runtime.h>
#include <math.h>

#define T 4096
#define BS 128
#define PT 4224            // padded rows per plane: T + 128 guard rows
#define SUBQ 1056          // PT/4, subplane length (mod-4 swizzle)
#define CAPC 1024          // coef cache entries (float4) per list
#define RCAP 512           // run cache entries per list

typedef unsigned long long ull;

// ---------------- device scratch ----------------
// swizzled padded planes: row t lives at (t&3)*SUBQ + (t>>2) + 32 within plane
__device__ float2 g_S2[(size_t)BS * 5 * PT];
__device__ float4 g_coefF[T + 8];             // (df, df, dfp, dfp), run-ordered
__device__ float4 g_coefG[T + 8];
__device__ int4   g_runF[2052];               // (m0, len, coefBase, 0)
__device__ int4   g_runG[2052];
__device__ int    g_nF, g_nG, g_nrunF, g_nrunG;

struct FParams {
    const float* W1[4];
    const float* b1[4];
    const float* W2[4];
    const float* b2[4];
};

// ---------------- math helpers ----------------
__device__ __forceinline__ void make_E(float z0, float z1,
                                       float a1x, float a1y, float a1z,
                                       float a2x, float a2y, float a2z,
                                       float e[9]) {
    float wx = a1x * z0 + a2x * z1;
    float wy = a1y * z0 + a2y * z1;
    float wz = a1z * z0 + a2z * z1;
    float th2 = wx * wx + wy * wy + wz * wz;
    float s, c, c2;
    if (th2 > 1e-6f) {
        float th = sqrtf(th2);
        float sn, cn;
        sincosf(th, &sn, &cn);
        s = sn / th;
        c = cn;
        c2 = (1.f - cn) / th2;
    } else {
        s = 1.f - th2 * (1.f / 6.f);
        c = 1.f - th2 * 0.5f;
        c2 = 0.5f - th2 * (1.f / 24.f);
    }
    e[0] = c + c2 * wx * wx;      e[1] = c2 * wx * wy - s * wz; e[2] = c2 * wx * wz + s * wy;
    e[3] = c2 * wy * wx + s * wz; e[4] = c + c2 * wy * wy;      e[5] = c2 * wy * wz - s * wx;
    e[6] = c2 * wz * wx - s * wy; e[7] = c2 * wz * wy + s * wx; e[8] = c + c2 * wz * wz;
}

__device__ __forceinline__ void mul_right(float X[9], const float e[9]) {
    #pragma unroll
    for (int r = 0; r < 3; r++) {
        float x0 = X[r * 3], x1 = X[r * 3 + 1], x2 = X[r * 3 + 2];
        X[r * 3 + 0] = x0 * e[0] + x1 * e[3] + x2 * e[6];
        X[r * 3 + 1] = x0 * e[1] + x1 * e[4] + x2 * e[7];
        X[r * 3 + 2] = x0 * e[2] + x1 * e[5] + x2 * e[8];
    }
}

__device__ __forceinline__ void mul_left(float X[9], const float L[9]) {
    #pragma unroll
    for (int cc = 0; cc < 3; cc++) {
        float x0 = X[cc], x1 = X[3 + cc], x2 = X[6 + cc];
        X[cc]     = L[0] * x0 + L[1] * x1 + L[2] * x2;
        X[3 + cc] = L[3] * x0 + L[4] * x1 + L[5] * x2;
        X[6 + cc] = L[6] * x0 + L[7] * x1 + L[8] * x2;
    }
}

// ---------------- K_main: filters/runs block (bid==BS) + pathdev blocks ----------------
__device__ void build_runs(const int* tapm, int cnt, int4* runs, int* nrun_out) {
    int nr = 0, i = 0;
    while (i < cnt) {
        int m0 = tapm[i];
        int j = i + 1;
        while (j < cnt && tapm[j] == tapm[j - 1] + 1) j++;
        runs[nr] = make_int4(m0, j - i, i, 0);
        nr++;
        i = j;
    }
    runs[nr] = make_int4(0x7fffffff, 0, 0, 0);  // sentinel
    *nrun_out = nr;
}

__global__ void __launch_bounds__(256) k_main(const float* __restrict__ x_data,
                                              const float* __restrict__ A1,
                                              const float* __restrict__ A2,
                                              FParams p) {
    extern __shared__ float smem[];
    int tid = threadIdx.x;

    if (blockIdx.x == BS) {
        float* sh = smem;                         // [4][T]
        int* tapmF = (int*)(smem + 4 * T);        // [T]
        int* tapmG = tapmF + T;                   // [T]
        for (int idx = tid; idx < 4 * T; idx += 256) {
            int f = idx >> 12;
            int i = idx & (T - 1);
            float tt = (f < 2) ? (float)(T - 1 - i) : (float)i;  // f, fp reversed
            const float* W1 = p.W1[f];
            const float* b1 = p.b1[f];
            const float* W2 = p.W2[f];
            float acc = p.b2[f][0];
            #pragma unroll
            for (int u = 0; u < 5; u++)
                acc += W2[u] * tanhf(W1[u] * tt + b1[u]);
            sh[f * T + i] = acc;
        }
        __syncthreads();
        int wid = tid >> 5, lane = tid & 31;
        if (wid < 2) {
            int fa = wid * 2, fb = fa + 1;
            float4* cdst = wid ? g_coefG : g_coefF;
            int* mdst = wid ? tapmG : tapmF;
            int cnt = 0;
            for (int base = 0; base < T; base += 32) {
                int m = base + lane;
                float da = (m == 0) ? sh[fa * T] : sh[fa * T + m] - sh[fa * T + m - 1];
                float db = (m == 0) ? sh[fb * T] : sh[fb * T + m] - sh[fb * T + m - 1];
                int act = (da != 0.f) || (db != 0.f);
                unsigned mask = __ballot_sync(0xffffffffu, act);
                if (act) {
                    int pos = cnt + __popc(mask & ((1u << lane) - 1u));
                    cdst[pos] = make_float4(da, da, db, db);  // pre-broadcast
                    mdst[pos] = m;
                }
                cnt += __popc(mask);
            }
            if (lane == 0) {
                if (wid == 0) g_nF = cnt; else g_nG = cnt;
            }
        }
        __syncthreads();
        if (tid == 0)  build_runs(tapmF, g_nF, g_runF, &g_nrunF);
        if (tid == 32) build_runs(tapmG, g_nG, g_runG, &g_nrunG);
        return;
    }

    // ---- pathdev block ----
    float* sx  = smem;          // 8192 floats
    float* smf = smem + 8192;   // 256*9 floats
    int b = blockIdx.x;

    {
        const float4* src = (const float4*)(x_data + (size_t)b * T * 2);
        float4* dst = (float4*)sx;
        #pragma unroll
        for (int i = tid; i < T * 2 / 4; i += 256) dst[i] = src[i];
    }

    float a1x = A1[7] - A1[5], a1y = A1[2] - A1[6], a1z = A1[3] - A1[1];
    float a2x = A2[7] - A2[5], a2y = A2[2] - A2[6], a2z = A2[3] - A2[1];
    __syncthreads();

    const int C = T / 256;  // 16
    int t0 = tid * C;

    float P[9] = {1, 0, 0, 0, 1, 0, 0, 0, 1};
    float CS[9] = {0, 0, 0, 0, 0, 0, 0, 0, 0};
    for (int i = 0; i < C; i++) {
        int t = t0 + i;
        if (t > 0) {
            float e[9];
            make_E(sx[2 * t], sx[2 * t + 1], a1x, a1y, a1z, a2x, a2y, a2z, e);
            mul_right(P, e);
        }
        #pragma unroll
        for (int d = 0; d < 9; d++) CS[d] += P[d];
    }

    float Pw[9];
    #pragma unroll
    for (int d = 0; d < 9; d++) { Pw[d] = P[d]; smf[tid * 9 + d] = P[d]; }
    for (int off = 1; off < 256; off <<= 1) {
        __syncthreads();
        float L[9];
        int has = tid >= off;
        if (has) {
            #pragma unroll
            for (int d = 0; d < 9; d++) L[d] = smf[(tid - off) * 9 + d];
        }
        __syncthreads();
        if (has) {
            mul_left(Pw, L);
            #pragma unroll
            for (int d = 0; d < 9; d++) smf[tid * 9 + d] = Pw[d];
        }
    }
    __syncthreads();
    float PM[9];
    if (tid > 0) {
        #pragma unroll
        for (int d = 0; d < 9; d++) PM[d] = smf[(tid - 1) * 9 + d];
    } else {
        #pragma unroll
        for (int d = 0; d < 9; d++) PM[d] = (d == 0 || d == 4 || d == 8) ? 1.f : 0.f;
    }
    __syncthreads();

    float CSg[9];
    #pragma unroll
    for (int i = 0; i < 3; i++)
        #pragma unroll
        for (int j = 0; j < 3; j++)
            CSg[3 * i + j] = PM[3 * i + 0] * CS[0 + j] + PM[3 * i + 1] * CS[3 + j] + PM[3 * i + 2] * CS[6 + j];

    float Aw[9];
    #pragma unroll
    for (int d = 0; d < 9; d++) { Aw[d] = CSg[d]; smf[tid * 9 + d] = CSg[d]; }
    for (int off = 1; off < 256; off <<= 1) {
        __syncthreads();
        float L[9];
        int has = tid >= off;
        if (has) {
            #pragma unroll
            for (int d = 0; d < 9; d++) L[d] = smf[(tid - off) * 9 + d];
        }
        __syncthreads();
        if (has) {
            #pragma unroll
            for (int d = 0; d < 9; d++) { Aw[d] += L[d]; smf[tid * 9 + d] = Aw[d]; }
        }
    }
    __syncthreads();
    float PS[9];
    if (tid > 0) {
        #pragma unroll
        for (int d = 0; d < 9; d++) PS[d] = smf[(tid - 1) * 9 + d];
    } else {
        #pragma unroll
        for (int d = 0; d < 9; d++) PS[d] = 0.f;
    }

    float X[9];
    #pragma unroll
    for (int d = 0; d < 9; d++) X[d] = PM[d];
    float2* Sb = g_S2 + (size_t)b * 5 * PT;
    for (int i = 0; i < C; i++) {
        int t = t0 + i;
        if (t > 0) {
            float e[9];
            make_E(sx[2 * t], sx[2 * t + 1], a1x, a1y, a1z, a2x, a2y, a2z, e);
            mul_right(X, e);
        }
        #pragma unroll
        for (int d = 0; d < 9; d++) PS[d] += X[d];
        int si = ((t & 3) * SUBQ) + (t >> 2) + 32;   // swizzled + pad offset
        // transpose-closed pairing: (0,4) (1,3) (8,-) (2,6) (5,7)
        Sb[0 * PT + si] = make_float2(PS[0], PS[4]);
        Sb[1 * PT + si] = make_float2(PS[1], PS[3]);
        Sb[2 * PT + si] = make_float2(PS[8], 0.f);
        Sb[3 * PT + si] = make_float2(PS[2], PS[6]);
        Sb[4 * PT + si] = make_float2(PS[5], PS[7]);
    }
}

// ---------------- K_final: guard-free sliding-window FIR, 16 warps ----------------
__device__ __forceinline__ ull f2pair(float a, float b) {
    ull r;
    asm("mov.b64 %0, {%1, %2};" : "=l"(r) : "f"(a), "f"(b));
    return r;
}
__device__ __forceinline__ ull f2bits(float2 v) {
    ull r;
    asm("mov.b64 %0, {%1, %2};" : "=l"(r) : "f"(v.x), "f"(v.y));
    return r;
}
__device__ __forceinline__ void fma2(ull& acc, ull a, ull b) {
    asm("fma.rn.f32x2 %0, %1, %2, %0;" : "+l"(acc) : "l"(a), "l"(b));
}
__device__ __forceinline__ void unpck(ull v, float& lo, float& hi) {
    asm("mov.b64 {%0, %1}, %2;" : "=f"(lo), "=f"(hi) : "l"(v));
}

template <int NP, bool SHC, bool SHR>
__device__ void walk(const float2* __restrict__ sSb,       // base of first plane
                     const float4* __restrict__ coefs,
                     const int4* __restrict__ runs, int nrun,
                     int k0, int warpKmax,
                     ull accA[NP][4], ull accB[NP][4]) {
    for (int ri = 0; ri < nrun; ri++) {
        int4 rn = SHR ? runs[ri] : __ldg(&runs[ri]);
        int m0 = rn.x;
        if (m0 > warpKmax) break;
        int L = min(rn.y, warpKmax - m0 + 1);
        const float4* cc = coefs + rn.z;

        int rtop = k0 + 128 - m0;   // padded row' of window slot j=0

        ull W[NP][4];
        #pragma unroll
        for (int j = 0; j < 4; j++) {
            int rp = rtop + j;
            int off = ((rp & 3) * SUBQ) + (rp >> 2);
            #pragma unroll
            for (int p = 0; p < NP; p++)
                W[p][j] = f2bits(sSb[p * PT + off]);
        }
        int offu[4];
        #pragma unroll
        for (int u = 0; u < 4; u++) {
            int rp = rtop - 1 - u;
            offu[u] = ((rp & 3) * SUBQ) + (rp >> 2);
        }

        int i = 0;
        for (; i + 4 <= L; i += 4) {
            #pragma unroll
            for (int u = 0; u < 4; u++) {
                float4 cf = SHC ? cc[i + u] : __ldg(&cc[i + u]);
                ull cy = f2pair(cf.x, cf.y);
                ull cz = f2pair(cf.z, cf.w);
                #pragma unroll
                for (int p = 0; p < NP; p++)
                    #pragma unroll
                    for (int j = 0; j < 4; j++) {
                        ull w = W[p][(j - u) & 3];
                        fma2(accA[p][j], w, cy);
                        fma2(accB[p][j], w, cz);
                    }
                #pragma unroll
                for (int p = 0; p < NP; p++)
                    W[p][(3 - u) & 3] = f2bits(sSb[p * PT + offu[u]]);
                offu[u] -= 1;
            }
        }
        #pragma unroll
        for (int u = 0; u < 3; u++) {
            if (i + u < L) {
                float4 cf = SHC ? cc[i + u] : __ldg(&cc[i + u]);
                ull cy = f2pair(cf.x, cf.y);
                ull cz = f2pair(cf.z, cf.w);
                #pragma unroll
                for (int p = 0; p < NP; p++)
                    #pragma unroll
                    for (int j = 0; j < 4; j++) {
                        ull w = W[p][(j - u) & 3];
                        fma2(accA[p][j], w, cy);
                        fma2(accB[p][j], w, cz);
                    }
            }
        }
    }
}

// run one (F,G) walk pair over NP planes starting at plane pb
template <int NP>
__device__ __forceinline__ void pass(const float2* __restrict__ sS, int pb,
                                     const float4* sCF, const float4* sCG,
                                     const int4* sRF, const int4* sRG,
                                     int nrF, int nrG,
                                     bool fitCF, bool fitCG, bool fitRF, bool fitRG,
                                     int k0, int warpKmax,
                                     ull aF[NP][4], ull aFp[NP][4],
                                     ull aG[NP][4], ull aGp[NP][4]) {
    #pragma unroll
    for (int p = 0; p < NP; p++)
        #pragma unroll
        for (int j = 0; j < 4; j++) { aF[p][j] = 0; aFp[p][j] = 0; aG[p][j] = 0; aGp[p][j] = 0; }

    const float2* sSb = sS + pb * PT;
    if (fitCF && fitRF)      walk<NP, true,  true >(sSb, sCF,     sRF,    nrF, k0, warpKmax, aF, aFp);
    else if (fitCF)          walk<NP, true,  false>(sSb, sCF,     g_runF, nrF, k0, warpKmax, aF, aFp);
    else                     walk<NP, false, false>(sSb, g_coefF, g_runF, nrF, k0, warpKmax, aF, aFp);
    if (fitCG && fitRG)      walk<NP, true,  true >(sSb, sCG,     sRG,    nrG, k0, warpKmax, aG, aGp);
    else if (fitCG)          walk<NP, true,  false>(sSb, sCG,     g_runG, nrG, k0, warpKmax, aG, aGp);
    else                     walk<NP, false, false>(sSb, g_coefG, g_runG, nrG, k0, warpKmax, aG, aGp);
}

__global__ void __launch_bounds__(512, 1) k_final(float* __restrict__ out) {
    extern __shared__ __align__(16) char smem_raw[];
    float2* sS  = (float2*)smem_raw;                  // 5*PT float2 = 168960 B
    float4* sCF = (float4*)(sS + 5 * PT);             // 16384 B
    float4* sCG = sCF + CAPC;                         // 16384 B
    int4*   sRF = (int4*)(sCG + CAPC);                // 8192 B
    int4*   sRG = sRF + RCAP;                         // 8192 B

    int q = blockIdx.x, b = blockIdx.y, tid = threadIdx.x;
    int wid = tid >> 5, lane = tid & 31;
    int chunk = wid * 2 + q;             // even/odd interleave balances tap work
    int k0 = chunk * 128 + lane * 4;
    int warpKmax = chunk * 128 + 127;

    // stage FULL S planes + zero pad rows
    {
        const float2* src = g_S2 + (size_t)b * 5 * PT;
        #pragma unroll
        for (int pp = 0; pp < 5; pp++)
            #pragma unroll
            for (int s = 0; s < 4; s++) {
                const float4* s4 = (const float4*)(src + pp * PT + s * SUBQ + 32);
                float4* d4 = (float4*)(sS + pp * PT + s * SUBQ + 32);
                for (int i = tid; i < 512; i += 512) d4[i] = s4[i];
            }
        for (int i = tid; i < 5 * 4 * 32; i += 512) {
            int pl = i >> 7, r = i & 127, s = r >> 5, e = r & 31;
            sS[pl * PT + s * SUBQ + e] = make_float2(0.f, 0.f);
        }
    }
    int nF = g_nF, nG = g_nG, nrF = g_nrunF, nrG = g_nrunG;
    bool fitCF = nF <= CAPC, fitCG = nG <= CAPC;
    bool fitRF = nrF <= RCAP, fitRG = nrG <= RCAP;
    if (fitCF) for (int i = tid; i < nF; i += 512) sCF[i] = g_coefF[i];
    if (fitCG) for (int i = tid; i < nG; i += 512) sCG[i] = g_coefG[i];
    if (fitRF) for (int i = tid; i < nrF; i += 512) sRF[i] = g_runF[i];
    if (fitRG) for (int i = tid; i < nrG; i += 512) sRG[i] = g_runG[i];
    __syncthreads();

    float* po = out + ((size_t)b * T + (size_t)k0) * 9;

    // ---- pass 1: planes 0,1 -> channels (0,4) noswap | (1,3) swap ----
    {
        ull aF[2][4], aFp[2][4], aG[2][4], aGp[2][4];
        pass<2>(sS, 0, sCF, sCG, sRF, sRG, nrF, nrG,
                fitCF, fitCG, fitRF, fitRG, k0, warpKmax, aF, aFp, aG, aGp);
        #pragma unroll
        for (int j = 0; j < 4; j++) {
            float fLo, fHi, pLo, pHi, gLo, gHi, qLo, qHi;
            unpck(aF[0][j], fLo, fHi);  unpck(aFp[0][j], pLo, pHi);
            unpck(aG[0][j], gLo, gHi);  unpck(aGp[0][j], qLo, qHi);
            po[j * 9 + 0] = fLo * gLo + pLo * qLo;
            po[j * 9 + 4] = fHi * gHi + pHi * qHi;
            unpck(aF[1][j], fLo, fHi);  unpck(aFp[1][j], pLo, pHi);
            unpck(aG[1][j], gLo, gHi);  unpck(aGp[1][j], qLo, qHi);
            po[j * 9 + 1] = fHi * gLo + pHi * qLo;   // swap for F terms
            po[j * 9 + 3] = fLo * gHi + pLo * qHi;
        }
    }

    // ---- pass 2: planes 2,3 -> channels (8) noswap | (2,6) swap ----
    {
        ull aF[2][4], aFp[2][4], aG[2][4], aGp[2][4];
        pass<2>(sS, 2, sCF, sCG, sRF, sRG, nrF, nrG,
                fitCF, fitCG, fitRF, fitRG, k0, warpKmax, aF, aFp, aG, aGp);
        #pragma unroll
        for (int j = 0; j < 4; j++) {
            float fLo, fHi, pLo, pHi, gLo, gHi, qLo, qHi;
            unpck(aF[0][j], fLo, fHi);  unpck(aFp[0][j], pLo, pHi);
            unpck(aG[0][j], gLo, gHi);  unpck(aGp[0][j], qLo, qHi);
            po[j * 9 + 8] = fLo * gLo + pLo * qLo;
            unpck(aF[1][j], fLo, fHi);  unpck(aFp[1][j], pLo, pHi);
            unpck(aG[1][j], gLo, gHi);  unpck(aGp[1][j], qLo, qHi);
            po[j * 9 + 2] = fHi * gLo + pHi * qLo;   // (2,6) swap
            po[j * 9 + 6] = fLo * gHi + pLo * qHi;
        }
    }

    // ---- pass 3: plane 4 -> channels (5,7) swap ----
    {
        ull aF[1][4], aFp[1][4], aG[1][4], aGp[1][4];
        pass<1>(sS, 4, sCF, sCG, sRF, sRG, nrF, nrG,
                fitCF, fitCG, fitRF, fitRG, k0, warpKmax, aF, aFp, aG, aGp);
        #pragma unroll
        for (int j = 0; j < 4; j++) {
            float fLo, fHi, pLo, pHi, gLo, gHi, qLo, qHi;
            unpck(aF[0][j], fLo, fHi);  unpck(aFp[0][j], pLo, pHi);
            unpck(aG[0][j], gLo, gHi);  unpck(aGp[0][j], qLo, qHi);
            po[j * 9 + 5] = fHi * gLo + pHi * qLo;   // (5,7) swap
            po[j * 9 + 7] = fLo * gHi + pLo * qHi;
        }
    }
}

// ---------------- launch ----------------
extern "C" void kernel_launch(void* const* d_in, const int* in_sizes, int n_in,
                              void* d_out, int out_size) {
    (void)in_sizes; (void)n_in; (void)out_size;
    const float* x  = (const float*)d_in[0];
    const float* A1 = (const float*)d_in[1];
    const float* A2 = (const float*)d_in[2];
    FParams p;
    for (int f = 0; f < 4; f++) {
        p.W1[f] = (const float*)d_in[3 + 4 * f + 0];
        p.b1[f] = (const float*)d_in[3 + 4 * f + 1];
        p.W2[f] = (const float*)d_in[3 + 4 * f + 2];
        p.b2[f] = (const float*)d_in[3 + 4 * f + 3];
    }

    const int SM1 = 4 * T * 4 + 2 * T * 4;  // 98304 (filters block); pathdev uses 41984
    cudaFuncSetAttribute(k_main, cudaFuncAttributeMaxDynamicSharedMemorySize, SM1);
    k_main<<<BS + 1, 256, SM1>>>(x, A1, A2, p);

    const int SM2 = 5 * PT * 8 + 2 * CAPC * 16 + 2 * RCAP * 16;  // 218112
    cudaFuncSetAttribute(k_final, cudaFuncAttributeMaxDynamicSharedMemorySize, SM2);
    k_final<<<dim3(2, BS), 512, SM2>>>((float*)d_out);
}